// round 10
// baseline (speedup 1.0000x reference)
#include <cuda_runtime.h>
#include <cuda_fp16.h>
#include <cstdint>
#include <cstddef>

#define DI __device__ __forceinline__
typedef unsigned long long ull;

static constexpr int ZDIM = 512;
static constexpr int MSZ  = 100;
static constexpr int NT   = 13;                      // n8 tiles (104 >= 100)
static constexpr int TSTEPS = ZDIM / 16;             // 32 k16-tiles
static constexpr int MROWS  = 256;                   // batch rows per CTA (2 m-tiles per warp)
static constexpr int EXP_STR   = 106;                // even (LDS.64 aligned), conflict-free residues
static constexpr int SA_FLOATS = MROWS * EXP_STR;    // 27136 floats = 108544 B
static constexpr int SC_FLOATS = 128 * EXP_STR;      // 13568 floats = 54272 B (per expm half)
static constexpr int SMEM_DYN  = (SA_FLOATS + SC_FLOATS) * 4;   // 162816 B
static constexpr int STAGE_U4  = NT * 32;            // 416 uint4 = 6656 B per k16 stage

// basis fragments, fragment-ordered: [t 0..31][nt 0..12][lane 0..31] = (b0h,b1h,b0l,b1l)
__device__ uint4 g_bfrag[TSTEPS * STAGE_U4];         // 212,992 B

DI void fma2(ull& d, ull a, ull b) { asm("fma.rn.f32x2 %0, %1, %2, %0;" : "+l"(d) : "l"(a), "l"(b)); }
DI ull pack2(float v) { ull r; asm("mov.b64 %0, {%1, %1};" : "=l"(r) : "f"(v)); return r; }
DI ull pk(float x, float y) { ull r; asm("mov.b64 %0, {%1, %2};" : "=l"(r) : "f"(x), "f"(y)); return r; }
DI float2 unpk(ull v) { float2 f; asm("mov.b64 {%0, %1}, %2;" : "=f"(f.x), "=f"(f.y) : "l"(v)); return f; }
DI ull lds2(const float* p) { float2 v = *(const float2*)p; return pk(v.x, v.y); }

DI uint32_t smem_u32(const void* p) {
    uint32_t a;
    asm("{ .reg .u64 t; cvta.to.shared.u64 t, %1; cvt.u32.u64 %0, t; }" : "=r"(a) : "l"(p));
    return a;
}
DI void cpasync16(uint32_t saddr, const void* g) {
    asm volatile("cp.async.cg.shared.global [%0], [%1], 16;" :: "r"(saddr), "l"(g));
}
DI void cpcommit() { asm volatile("cp.async.commit_group;" ::: "memory"); }
DI void cpwait2()  { asm volatile("cp.async.wait_group 2;" ::: "memory"); }
DI void cpwait0()  { asm volatile("cp.async.wait_group 0;" ::: "memory"); }

// split fp32 pair into f16x2 hi + f16x2 residual-lo
DI void cvt_split(float x, float y, uint32_t& hi, uint32_t& lo) {
    __half2 h = __floats2half2_rn(x, y);
    __half2 l = __floats2half2_rn(x - __low2float(h), y - __high2float(h));
    hi = *reinterpret_cast<uint32_t*>(&h);
    lo = *reinterpret_cast<uint32_t*>(&l);
}

DI void mma16816(float* d, const uint32_t* a, uint32_t b0, uint32_t b1) {
    asm volatile("mma.sync.aligned.m16n8k16.row.col.f32.f16.f16.f32 "
        "{%0,%1,%2,%3}, {%4,%5,%6,%7}, {%8,%9}, {%0,%1,%2,%3};"
        : "+f"(d[0]), "+f"(d[1]), "+f"(d[2]), "+f"(d[3])
        : "r"(a[0]), "r"(a[1]), "r"(a[2]), "r"(a[3]), "r"(b0), "r"(b1));
}

// ---------- pre-kernel: convert basis -> fragment-ordered split-fp16 global array ----------
extern "C" __global__ void __launch_bounds__(256)
conv_basis(const float* __restrict__ basis)
{
    int s = blockIdx.x * 256 + threadIdx.x;          // 0 .. 13311
    if (s >= TSTEPS * STAGE_U4) return;
    int t  = s / STAGE_U4;
    int r  = s - t * STAGE_U4;
    int nt = r >> 5;
    int ln = r & 31;
    int qq = ln & 3;
    int n  = nt * 8 + (ln >> 2);
    uint4 val = make_uint4(0u, 0u, 0u, 0u);
    if (n < MSZ) {
        int k0 = t * 16 + 2 * qq;
        float v0 = basis[(size_t)k0 * MSZ + n];
        float v1 = basis[(size_t)(k0 + 1) * MSZ + n];
        float v2 = basis[(size_t)(k0 + 8) * MSZ + n];
        float v3 = basis[(size_t)(k0 + 9) * MSZ + n];
        cvt_split(v0, v1, val.x, val.z);
        cvt_split(v2, v3, val.y, val.w);
    }
    g_bfrag[s] = val;
}

// ---------- fused kernel: GEMM (2 m-tiles/warp, split-fp16 3-pass) + expm (2 halves) ----------
extern "C" __global__ void __launch_bounds__(256, 1)
lie_fused(const float* __restrict__ z, float* __restrict__ out)
{
    extern __shared__ float smem[];
    float* sA = smem;                 // lie_alg / W working set (256 x EXP_STR)
    float* sC = smem + SA_FLOATS;     // GEMM: B ring; expm: A^3 buffer (128 x EXP_STR)
    const uint32_t ring_base = smem_u32(sC);

    const int tid = threadIdx.x, lane = tid & 31, w = tid >> 5;
    const int g = lane >> 2, q = lane & 3;
    const size_t rowBase = (size_t)blockIdx.x * MROWS;
    // warp owns rows w*32 .. w*32+31: m-tile0 = rows +0..15, m-tile1 = rows +16..31
    const size_t row0 = rowBase + w * 32 + g;
    const float* za = z + row0 * ZDIM;            // m0, row g
    const float* zb = za + 8 * ZDIM;              // m0, row g+8
    const float* zc = za + 16 * ZDIM;             // m1, row g
    const float* zd = za + 24 * ZDIM;             // m1, row g+8

    // ================= GEMM phase =================
    float acc0[NT][4], acc1[NT][4];
#pragma unroll
    for (int nt = 0; nt < NT; nt++)
#pragma unroll
        for (int e = 0; e < 4; e++) { acc0[nt][e] = 0.f; acc1[nt][e] = 0.f; }

    auto issue_stage = [&](int s) {
        const uint4* gsrc = g_bfrag + (size_t)s * STAGE_U4;
        uint32_t sdst = ring_base + (uint32_t)(s & 3) * (STAGE_U4 * 16);
        cpasync16(sdst + tid * 16, gsrc + tid);
        int i2 = tid + 256;
        if (i2 < STAGE_U4) cpasync16(sdst + i2 * 16, gsrc + i2);
    };

    issue_stage(0); cpcommit();
    issue_stage(1); cpcommit();
    issue_stage(2); cpcommit();

    // prefetch first k16-tile of z fragments (8 x float2)
    float2 pa0, pa1, pb0, pb1, pc0, pc1, pd0, pd1;
    {
        const int kb = 2 * q;
        pa0 = *(const float2*)(za + kb); pa1 = *(const float2*)(za + kb + 8);
        pb0 = *(const float2*)(zb + kb); pb1 = *(const float2*)(zb + kb + 8);
        pc0 = *(const float2*)(zc + kb); pc1 = *(const float2*)(zc + kb + 8);
        pd0 = *(const float2*)(zd + kb); pd1 = *(const float2*)(zd + kb + 8);
    }

    for (int t = 0; t < TSTEPS; t++) {
        cpwait2();          // stage t landed (one commit per iteration)
        __syncthreads();    // visibility of stage t; all reads of slot (t-1)&3 done
        if (t + 3 < TSTEPS) issue_stage(t + 3);
        cpcommit();

        uint32_t Ah0[4], Al0[4], Ah1[4], Al1[4];
        cvt_split(pa0.x, pa0.y, Ah0[0], Al0[0]);
        cvt_split(pb0.x, pb0.y, Ah0[1], Al0[1]);
        cvt_split(pa1.x, pa1.y, Ah0[2], Al0[2]);
        cvt_split(pb1.x, pb1.y, Ah0[3], Al0[3]);
        cvt_split(pc0.x, pc0.y, Ah1[0], Al1[0]);
        cvt_split(pd0.x, pd0.y, Ah1[1], Al1[1]);
        cvt_split(pc1.x, pc1.y, Ah1[2], Al1[2]);
        cvt_split(pd1.x, pd1.y, Ah1[3], Al1[3]);
        if (t + 1 < TSTEPS) {
            const int kb = (t + 1) * 16 + 2 * q;
            pa0 = *(const float2*)(za + kb); pa1 = *(const float2*)(za + kb + 8);
            pb0 = *(const float2*)(zb + kb); pb1 = *(const float2*)(zb + kb + 8);
            pc0 = *(const float2*)(zc + kb); pc1 = *(const float2*)(zc + kb + 8);
            pd0 = *(const float2*)(zd + kb); pd1 = *(const float2*)(zd + kb + 8);
        }

        const uint4* bs = (const uint4*)sC + (size_t)(t & 3) * STAGE_U4 + lane;

        // group 1: nt 0..6 — one LDS.128 per nt serves BOTH m-tiles (dep distance 14)
        {
            uint4 bb[7];
#pragma unroll
            for (int j = 0; j < 7; j++) bb[j] = bs[j * 32];
#pragma unroll
            for (int j = 0; j < 7; j++) mma16816(acc0[j], Ah0, bb[j].x, bb[j].y);
#pragma unroll
            for (int j = 0; j < 7; j++) mma16816(acc1[j], Ah1, bb[j].x, bb[j].y);
#pragma unroll
            for (int j = 0; j < 7; j++) mma16816(acc0[j], Al0, bb[j].x, bb[j].y);
#pragma unroll
            for (int j = 0; j < 7; j++) mma16816(acc1[j], Al1, bb[j].x, bb[j].y);
#pragma unroll
            for (int j = 0; j < 7; j++) mma16816(acc0[j], Ah0, bb[j].z, bb[j].w);
#pragma unroll
            for (int j = 0; j < 7; j++) mma16816(acc1[j], Ah1, bb[j].z, bb[j].w);
        }
        // group 2: nt 7..12
        {
            uint4 bb[6];
#pragma unroll
            for (int j = 0; j < 6; j++) bb[j] = bs[(7 + j) * 32];
#pragma unroll
            for (int j = 0; j < 6; j++) mma16816(acc0[7 + j], Ah0, bb[j].x, bb[j].y);
#pragma unroll
            for (int j = 0; j < 6; j++) mma16816(acc1[7 + j], Ah1, bb[j].x, bb[j].y);
#pragma unroll
            for (int j = 0; j < 6; j++) mma16816(acc0[7 + j], Al0, bb[j].x, bb[j].y);
#pragma unroll
            for (int j = 0; j < 6; j++) mma16816(acc1[7 + j], Al1, bb[j].x, bb[j].y);
#pragma unroll
            for (int j = 0; j < 6; j++) mma16816(acc0[7 + j], Ah0, bb[j].z, bb[j].w);
#pragma unroll
            for (int j = 0; j < 6; j++) mma16816(acc1[7 + j], Ah1, bb[j].z, bb[j].w);
        }
    }

    // epilogue: fragments -> sA in expm layout
    {
        const int rl0 = w * 32 + g;
#pragma unroll
        for (int nt = 0; nt < NT; nt++) {
            int col = nt * 8 + 2 * q;
            if (col < MSZ) {
                *(float2*)(sA + (rl0     ) * EXP_STR + col) = make_float2(acc0[nt][0], acc0[nt][1]);
                *(float2*)(sA + (rl0 +  8) * EXP_STR + col) = make_float2(acc0[nt][2], acc0[nt][3]);
                *(float2*)(sA + (rl0 + 16) * EXP_STR + col) = make_float2(acc1[nt][0], acc1[nt][1]);
                *(float2*)(sA + (rl0 + 24) * EXP_STR + col) = make_float2(acc1[nt][2], acc1[nt][3]);
            }
        }
    }
    cpwait0();           // drain async groups before sC reuse
    __syncthreads();     // lie_alg complete in sA; ring dead

    // ================= expm: two halves of 128 matrices, 2 threads/matrix =================
    // E = I + A + A^2/2 + A^3/6 + A^3*(A/24 + A^2/120 + A^3/720)
    for (int half = 0; half < 2; half++) {
        const int m  = tid >> 1;       // local matrix 0..127 within half
        const int h  = tid & 1;
        const int i0 = 5 * h;
        const int mbA = (half * 128 + m) * EXP_STR;
        const int mbC = m * EXP_STR;

        ull acc2[5][5];
#pragma unroll
        for (int ii = 0; ii < 5; ii++)
#pragma unroll
            for (int jp = 0; jp < 5; jp++) acc2[ii][jp] = 0ull;

        // A^2 (own rows) -> acc2
#pragma unroll
        for (int kp = 0; kp < 5; kp++) {
            const int k0 = 2 * kp, k1 = k0 + 1;
            ull r0[5], r1[5];
#pragma unroll
            for (int jp = 0; jp < 5; jp++) {
                r0[jp] = lds2(sA + mbA + k0 * 10 + 2 * jp);
                r1[jp] = lds2(sA + mbA + k1 * 10 + 2 * jp);
            }
#pragma unroll
            for (int ii = 0; ii < 5; ii++) {
                float2 za2 = *(const float2*)(sA + mbA + (i0 + ii) * 10 + k0);
                ull z0 = pack2(za2.x), z1 = pack2(za2.y);
#pragma unroll
                for (int jp = 0; jp < 5; jp++) { fma2(acc2[ii][jp], z0, r0[jp]); fma2(acc2[ii][jp], z1, r1[jp]); }
            }
        }

        // A^3 = A^2 @ A -> sC (two row-groups to bound register pressure)
#pragma unroll
        for (int grp = 0; grp < 2; grp++) {
            const int gbase = grp * 3;
            const int rows  = grp == 0 ? 3 : 2;
            ull a3[3][5];
#pragma unroll
            for (int ii = 0; ii < 3; ii++)
#pragma unroll
                for (int jp = 0; jp < 5; jp++) a3[ii][jp] = 0ull;
#pragma unroll
            for (int kp = 0; kp < 5; kp++) {
                const int k0 = 2 * kp, k1 = k0 + 1;
                ull r0[5], r1[5];
#pragma unroll
                for (int jp = 0; jp < 5; jp++) {
                    r0[jp] = lds2(sA + mbA + k0 * 10 + 2 * jp);
                    r1[jp] = lds2(sA + mbA + k1 * 10 + 2 * jp);
                }
#pragma unroll
                for (int ii = 0; ii < 3; ii++) {
                    if (ii < rows) {
                        float2 f = unpk(acc2[gbase + ii][kp]);
                        ull z0 = pack2(f.x), z1 = pack2(f.y);
#pragma unroll
                        for (int jp = 0; jp < 5; jp++) { fma2(a3[ii][jp], z0, r0[jp]); fma2(a3[ii][jp], z1, r1[jp]); }
                    }
                }
            }
#pragma unroll
            for (int ii = 0; ii < 3; ii++) {
                if (ii < rows) {
                    const int gi = i0 + gbase + ii;
#pragma unroll
                    for (int jp = 0; jp < 5; jp++)
                        *(float2*)(sC + mbC + gi * 10 + 2 * jp) = unpk(a3[ii][jp]);
                }
            }
        }
        __syncthreads();   // all matmul reads of A (this half) complete before W overwrite

        // W = A/24 + A^2/120 + A^3/720 -> sA (own rows); U = I + A + A^2/2 + A^3/6 -> acc2
        {
            const float c2 = 0.5f, c3 = 1.f/6.f, c4 = 1.f/24.f, c5 = 1.f/120.f, c6 = 1.f/720.f;
#pragma unroll
            for (int ii = 0; ii < 5; ii++) {
                const int gi = i0 + ii;
#pragma unroll
                for (int jp = 0; jp < 5; jp++) {
                    float2 a  = *(const float2*)(sA + mbA + gi * 10 + 2 * jp);
                    float2 b3 = *(const float2*)(sC + mbC + gi * 10 + 2 * jp);
                    float2 b2 = unpk(acc2[ii][jp]);
                    float wx = a.x * c4 + b2.x * c5 + b3.x * c6;
                    float wy = a.y * c4 + b2.y * c5 + b3.y * c6;
                    float ux = (gi == 2 * jp     ? 1.f : 0.f) + a.x + b2.x * c2 + b3.x * c3;
                    float uy = (gi == 2 * jp + 1 ? 1.f : 0.f) + a.y + b2.y * c2 + b3.y * c3;
                    *(float2*)(sA + mbA + gi * 10 + 2 * jp) = make_float2(wx, wy);
                    acc2[ii][jp] = pk(ux, uy);
                }
            }
        }
        __syncthreads();   // W complete in sA

        // E = U + A^3 @ W  (A^3 from sC own rows; W rows from sA)
#pragma unroll
        for (int kp = 0; kp < 5; kp++) {
            const int k0 = 2 * kp, k1 = k0 + 1;
            ull r0[5], r1[5];
#pragma unroll
            for (int jp = 0; jp < 5; jp++) {
                r0[jp] = lds2(sA + mbA + k0 * 10 + 2 * jp);
                r1[jp] = lds2(sA + mbA + k1 * 10 + 2 * jp);
            }
#pragma unroll
            for (int ii = 0; ii < 5; ii++) {
                float2 f = *(const float2*)(sC + mbC + (i0 + ii) * 10 + k0);
                ull z0 = pack2(f.x), z1 = pack2(f.y);
#pragma unroll
                for (int jp = 0; jp < 5; jp++) { fma2(acc2[ii][jp], z0, r0[jp]); fma2(acc2[ii][jp], z1, r1[jp]); }
            }
        }

        // store own 5 rows (50 contiguous floats)
        float* op = out + (rowBase + half * 128 + m) * MSZ + i0 * 10;
#pragma unroll
        for (int ii = 0; ii < 5; ii++)
#pragma unroll
            for (int jp = 0; jp < 5; jp++)
                *(float2*)(op + ii * 10 + 2 * jp) = unpk(acc2[ii][jp]);

        if (half == 0) __syncthreads();   // sC reads done before half-1 overwrites it
    }
}

// ---------------- launch ----------------
extern "C" void kernel_launch(void* const* d_in, const int* in_sizes, int n_in,
                              void* d_out, int out_size)
{
    const float* z     = (const float*)d_in[0];   // [B, 512]
    const float* basis = (const float*)d_in[1];   // [512, 10, 10]
    float* out = (float*)d_out;                   // [B, 10, 10]

    int B = in_sizes[0] / ZDIM;                   // 131072

    cudaFuncSetAttribute(lie_fused, cudaFuncAttributeMaxDynamicSharedMemorySize, SMEM_DYN);

    conv_basis<<<52, 256>>>(basis);               // 13312 fragment slots
    lie_fused<<<B / MROWS, 256, SMEM_DYN>>>(z, out);
}